// round 3
// baseline (speedup 1.0000x reference)
#include <cuda_runtime.h>
#include <cstdint>

// ============================================================================
// EdgeUpdate: out[e] = relu( concat(nf[src[e]]+nf[dst[e]], ef[e]) @ W^T + b )
// E=640000, NODE_DIM=128, EDGE_IN=128, EDGE_OUT=128  (GEMM: M=E, N=128, K=256)
//
// NOTE: reference declares edge_index int64, but JAX default (no x64) silently
// downcasts to int32 -> the buffer is int32[2*E]. Reading it as int64 was the
// cause of the round-2 illegal memory access.
//
// Toolchain targets plain sm_103 (no 'a') -> tcgen05 unavailable. Use baseline
// mma.sync.m16n8k8 tf32 (sm_80+): single pass, rel_err ~3e-4 (< 1e-3).
//
// Persistent CTAs. W resident in smem as tf32 (cvt.rna), pad-stride for
// conflict-free fragment LDS. Per 128-edge tile: phase0 = gathered node pair
// (K 0..127), phase1 = edge features (K 128..255, register-prefetched during
// phase-0 MMA). fp32 accumulation in registers across both phases.
// ============================================================================

static constexpr int WS_STRIDE = 260;                    // floats; (4g+t)%32 conflict-free
static constexpr int AS_STRIDE = 132;                    // floats; (4g+t)%32 conflict-free
static constexpr int SM_W_OFF  = 256;                    // floats (bias in [0,128))
static constexpr int SM_A_OFF  = SM_W_OFF + 128 * WS_STRIDE;   // 33536
static constexpr int SM_FLOATS = SM_A_OFF + 128 * AS_STRIDE;   // 50432
static constexpr int SM_BYTES  = SM_FLOATS * 4;                // 201728

#define CVT_TF32(u, f) asm("cvt.rna.tf32.f32 %0, %1;" : "=r"(u) : "f"(f))

__device__ __forceinline__ void mma_tf32(float* d, const uint32_t* a,
                                         const uint32_t* b) {
    asm volatile(
        "mma.sync.aligned.m16n8k8.row.col.f32.tf32.tf32.f32 "
        "{%0,%1,%2,%3}, {%4,%5,%6,%7}, {%8,%9}, {%0,%1,%2,%3};"
        : "+f"(d[0]), "+f"(d[1]), "+f"(d[2]), "+f"(d[3])
        : "r"(a[0]), "r"(a[1]), "r"(a[2]), "r"(a[3]), "r"(b[0]), "r"(b[1]));
}

// Convert float4 -> 4 tf32 words packed as uint4
__device__ __forceinline__ uint4 tf32x4(float4 v) {
    uint32_t u0, u1, u2, u3;
    CVT_TF32(u0, v.x); CVT_TF32(u1, v.y); CVT_TF32(u2, v.z); CVT_TF32(u3, v.w);
    return make_uint4(u0, u1, u2, u3);
}

__global__ void __launch_bounds__(256, 1)
edge_update_kernel(const float* __restrict__ nf,
                   const int* __restrict__ ei,      // int32[2*E] (JAX x64 off)
                   const float* __restrict__ ef,
                   const float* __restrict__ W,
                   const float* __restrict__ bias,
                   float* __restrict__ out, int E) {
    extern __shared__ float sm[];
    float* bsm = sm;
    float* Ws  = sm + SM_W_OFF;
    float* As  = sm + SM_A_OFF;

    const int tid = threadIdx.x;
    const int wid = tid >> 5;
    const int lid = tid & 31;
    const int g   = lid >> 2;      // group (row / n index in frags)
    const int t   = lid & 3;       // thread-in-group (k index in frags)
    const int mw  = (wid >> 2) * 64;   // warp M offset: 0 / 64
    const int nw  = (wid & 3) * 32;    // warp N offset: 0/32/64/96

    if (tid < 128) bsm[tid] = bias[tid];

    // ---- Load W -> smem as tf32, padded stride (one time) ----
    for (int idx = tid; idx < 128 * 64; idx += 256) {
        const int r  = idx >> 6;            // W row (n), 0..127
        const int c4 = (idx & 63) << 2;     // col (k), step 4
        uint4 u = tf32x4(*(const float4*)(W + r * 256 + c4));
        *(uint4*)(Ws + r * WS_STRIDE + c4) = u;
    }
    __syncthreads();

    const int ntiles = (E + 127) >> 7;
    const int ar = tid >> 1;    // A-tile row this thread fills (0..127)
    const int ah = tid & 1;     // K-half (64 floats)
    float* arow = As + ar * AS_STRIDE + ah * 64;

    for (int tile = blockIdx.x; tile < ntiles; tile += gridDim.x) {
        const int e0 = tile << 7;
        const int e  = e0 + ar;
        const int eg = (e < E) ? e : (E - 1);

        float acc[4][4][4] = {};

        // ---------- Phase 0 fill: nf[src] + nf[dst] ----------
        {
            const int s  = ei[eg];
            const int dd = ei[(size_t)E + eg];
            const float4* sp = (const float4*)(nf + (size_t)s  * 128 + ah * 64);
            const float4* dp = (const float4*)(nf + (size_t)dd * 128 + ah * 64);
#pragma unroll
            for (int i = 0; i < 16; i++) {
                float4 a = sp[i], b = dp[i];
                float4 x = make_float4(a.x + b.x, a.y + b.y, a.z + b.z, a.w + b.w);
                ((uint4*)arow)[i] = tf32x4(x);
            }
        }
        __syncthreads();

        // Prefetch edge features into registers (hidden under phase-0 MMA)
        float4 v[16];
        {
            const float4* p = (const float4*)(ef + (size_t)eg * 128 + ah * 64);
#pragma unroll
            for (int i = 0; i < 16; i++) v[i] = p[i];
        }

        // ---------- MMA phase 0: K 0..127 ----------
        {
            const float* Wp = Ws;
#pragma unroll
            for (int ks = 0; ks < 16; ks++) {
                uint32_t a[4][4];
#pragma unroll
                for (int i = 0; i < 4; i++) {
                    const float* p = As + (mw + 16 * i + g) * AS_STRIDE + ks * 8 + t;
                    a[i][0] = __float_as_uint(p[0]);
                    a[i][1] = __float_as_uint(p[8 * AS_STRIDE]);
                    a[i][2] = __float_as_uint(p[4]);
                    a[i][3] = __float_as_uint(p[8 * AS_STRIDE + 4]);
                }
                uint32_t b[4][2];
#pragma unroll
                for (int j = 0; j < 4; j++) {
                    const float* q = Wp + (nw + 8 * j + g) * WS_STRIDE + ks * 8 + t;
                    b[j][0] = __float_as_uint(q[0]);
                    b[j][1] = __float_as_uint(q[4]);
                }
#pragma unroll
                for (int i = 0; i < 4; i++)
#pragma unroll
                    for (int j = 0; j < 4; j++) mma_tf32(acc[i][j], a[i], b[j]);
            }
        }
        __syncthreads();

        // ---------- Phase 1 fill: edge features ----------
#pragma unroll
        for (int i = 0; i < 16; i++) ((uint4*)arow)[i] = tf32x4(v[i]);
        __syncthreads();

        // ---------- MMA phase 1: K 128..255 ----------
        {
            const float* Wp = Ws + 128;
#pragma unroll
            for (int ks = 0; ks < 16; ks++) {
                uint32_t a[4][4];
#pragma unroll
                for (int i = 0; i < 4; i++) {
                    const float* p = As + (mw + 16 * i + g) * AS_STRIDE + ks * 8 + t;
                    a[i][0] = __float_as_uint(p[0]);
                    a[i][1] = __float_as_uint(p[8 * AS_STRIDE]);
                    a[i][2] = __float_as_uint(p[4]);
                    a[i][3] = __float_as_uint(p[8 * AS_STRIDE + 4]);
                }
                uint32_t b[4][2];
#pragma unroll
                for (int j = 0; j < 4; j++) {
                    const float* q = Wp + (nw + 8 * j + g) * WS_STRIDE + ks * 8 + t;
                    b[j][0] = __float_as_uint(q[0]);
                    b[j][1] = __float_as_uint(q[4]);
                }
#pragma unroll
                for (int i = 0; i < 4; i++)
#pragma unroll
                    for (int j = 0; j < 4; j++) mma_tf32(acc[i][j], a[i], b[j]);
            }
        }

        // ---------- Epilogue: bias + relu + store ----------
#pragma unroll
        for (int j = 0; j < 4; j++) {
            const int col = nw + 8 * j + 2 * t;
            const float b0 = bsm[col], b1 = bsm[col + 1];
#pragma unroll
            for (int i = 0; i < 4; i++) {
                const int r0 = e0 + mw + 16 * i + g;
                if (r0 < E) {
                    float2 o;
                    o.x = fmaxf(acc[i][j][0] + b0, 0.f);
                    o.y = fmaxf(acc[i][j][1] + b1, 0.f);
                    *(float2*)(out + (size_t)r0 * 128 + col) = o;
                }
                if (r0 + 8 < E) {
                    float2 o;
                    o.x = fmaxf(acc[i][j][2] + b0, 0.f);
                    o.y = fmaxf(acc[i][j][3] + b1, 0.f);
                    *(float2*)(out + (size_t)(r0 + 8) * 128 + col) = o;
                }
            }
        }
        __syncthreads();   // all warps done reading As before next tile's fill
    }
}

extern "C" void kernel_launch(void* const* d_in, const int* in_sizes, int n_in,
                              void* d_out, int out_size) {
    const float* nf = (const float*)d_in[0];
    const int*   ei = (const int*)d_in[1];     // int32 (see note above)
    const float* ef = (const float*)d_in[2];
    const float* W  = (const float*)d_in[3];
    const float* b  = (const float*)d_in[4];
    float* out = (float*)d_out;

    const int E = in_sizes[2] / 128;

    cudaFuncSetAttribute(edge_update_kernel,
                         cudaFuncAttributeMaxDynamicSharedMemorySize, SM_BYTES);

    int dev = 0, sms = 148;
    cudaGetDevice(&dev);
    cudaDeviceGetAttribute(&sms, cudaDevAttrMultiProcessorCount, dev);

    const int ntiles = (E + 127) / 128;
    const int grid = (sms < ntiles) ? sms : ntiles;

    edge_update_kernel<<<grid, 256, SM_BYTES>>>(nf, ei, ef, W, b, out, E);
}

// round 4
// speedup vs baseline: 1.1019x; 1.1019x over previous
#include <cuda_runtime.h>
#include <cstdint>

// ============================================================================
// EdgeUpdate: out[e] = relu( concat(nf[src[e]]+nf[dst[e]], ef[e]) @ W^T + b )
// GEMM: M=E (640000), N=128, K=256. tf32 mma.m16n8k8, fp32 accumulate.
//
// R4: 512 threads (16 warps, 4Mx4N grid of 32x32 warp tiles), packed float4
// fragment layout in smem (1 LDS.128 = fragments for 2 K-steps), bank swizzle
// t^(q>>1), no register prefetch (kills R3's spills: regs 255 -> ~110).
//
// Packed layout per 128-K phase:  entry16B[row][q][t] =
//   ( X[16q+t], X[16q+t+4], X[16q+8+t], X[16q+12+t] ) , q=0..7, t=0..3
// address(float) = row*144 + q*16 + (t ^ (q>>1))*4
// ============================================================================

static constexpr int FSTR  = 144;                       // floats per packed row
static constexpr int SM_A  = 128;                       // after bias
static constexpr int SM_W  = SM_A + 128 * FSTR;         // two phase arrays follow
static constexpr int SM_FLOATS = SM_W + 2 * 128 * FSTR; // 55424
static constexpr int SM_BYTES  = SM_FLOATS * 4;         // 221696

#define CVT_TF32(u, f) asm("cvt.rna.tf32.f32 %0, %1;" : "=r"(u) : "f"(f))

__device__ __forceinline__ void mma_tf32(float* d, uint32_t a0, uint32_t a1,
                                         uint32_t a2, uint32_t a3,
                                         uint32_t b0, uint32_t b1) {
    asm volatile(
        "mma.sync.aligned.m16n8k8.row.col.f32.tf32.tf32.f32 "
        "{%0,%1,%2,%3}, {%4,%5,%6,%7}, {%8,%9}, {%0,%1,%2,%3};"
        : "+f"(d[0]), "+f"(d[1]), "+f"(d[2]), "+f"(d[3])
        : "r"(a0), "r"(a1), "r"(a2), "r"(a3), "r"(b0), "r"(b1));
}

__device__ __forceinline__ uint4 tf32q(float x0, float x1, float x2, float x3) {
    uint32_t u0, u1, u2, u3;
    CVT_TF32(u0, x0); CVT_TF32(u1, x1); CVT_TF32(u2, x2); CVT_TF32(u3, x3);
    return make_uint4(u0, u1, u2, u3);
}

__global__ void __launch_bounds__(512, 1)
edge_update_kernel(const float* __restrict__ nf,
                   const int* __restrict__ ei,      // int32[2*E] (JAX x64 off)
                   const float* __restrict__ ef,
                   const float* __restrict__ W,
                   const float* __restrict__ bias,
                   float* __restrict__ out, int E) {
    extern __shared__ float sm[];
    float* bsm = sm;
    float* As  = sm + SM_A;
    float* Ws  = sm + SM_W;

    const int tid = threadIdx.x;
    const int wid = tid >> 5;
    const int lid = tid & 31;
    const int g   = lid >> 2;          // 0..7
    const int t   = lid & 3;           // 0..3
    const int mw  = (wid >> 2) * 32;   // warp M offset 0/32/64/96
    const int nw  = (wid & 3) * 32;    // warp N offset 0/32/64/96

    if (tid < 128) bsm[tid] = bias[tid];

    // ---- One-time W -> packed tf32 smem (2 phase arrays) ----
    {
        const int n  = tid & 127;
        const int ph = (tid >> 7) & 1;
        const int s  = tid >> 8;                 // k sub-half within phase
        float x[64];
        const float4* wp = (const float4*)(W + n * 256 + ph * 128 + s * 64);
#pragma unroll
        for (int i = 0; i < 16; i++) {
            float4 v = wp[i];
            x[4 * i] = v.x; x[4 * i + 1] = v.y; x[4 * i + 2] = v.z; x[4 * i + 3] = v.w;
        }
        float* dst = Ws + ph * (128 * FSTR) + n * FSTR;
#pragma unroll
        for (int qp = 0; qp < 4; qp++) {
            const int q = 4 * s + qp;
            const int sw = (q >> 1) & 3;
#pragma unroll
            for (int tt = 0; tt < 4; tt++) {
                uint4 u = tf32q(x[16 * qp + tt], x[16 * qp + tt + 4],
                                x[16 * qp + tt + 8], x[16 * qp + tt + 12]);
                *(uint4*)(dst + q * 16 + (tt ^ sw) * 4) = u;
            }
        }
    }
    __syncthreads();

    const int ntiles = (E + 127) >> 7;
    const int ar = tid >> 2;           // A fill row 0..127
    const int qh = tid & 3;            // k quarter (32 floats)
    float* arow = As + ar * FSTR;

    // per-thread fragment base pointers
    const float* a_base = As + (size_t)(mw + g) * FSTR;
    const float* b_base0 = Ws + (size_t)(nw + g) * FSTR;
    const float* b_base1 = b_base0 + 128 * FSTR;

    for (int tile = blockIdx.x; tile < ntiles; tile += gridDim.x) {
        const int e0 = tile << 7;
        const int e  = e0 + ar;
        const int eg = (e < E) ? e : (E - 1);

        float acc[2][4][4] = {};

        // ---------- Phase 0 fill: nf[src] + nf[dst] (32 k per thread) ----------
        {
            const int s  = ei[eg];
            const int dd = ei[(size_t)E + eg];
            const float4* sp = (const float4*)(nf + (size_t)s  * 128 + qh * 32);
            const float4* dp = (const float4*)(nf + (size_t)dd * 128 + qh * 32);
            float x[32];
#pragma unroll
            for (int i = 0; i < 8; i++) {
                float4 a = sp[i], b = dp[i];
                x[4 * i]     = a.x + b.x; x[4 * i + 1] = a.y + b.y;
                x[4 * i + 2] = a.z + b.z; x[4 * i + 3] = a.w + b.w;
            }
#pragma unroll
            for (int qp = 0; qp < 2; qp++) {
                const int q = 2 * qh + qp;
#pragma unroll
                for (int tt = 0; tt < 4; tt++) {
                    uint4 u = tf32q(x[16 * qp + tt], x[16 * qp + tt + 4],
                                    x[16 * qp + tt + 8], x[16 * qp + tt + 12]);
                    *(uint4*)(arow + q * 16 + (tt ^ qh) * 4) = u;
                }
            }
        }
        __syncthreads();

        // ---------- MMA phase 0 ----------
#pragma unroll
        for (int q = 0; q < 8; q++) {
            const int sw = q * 16 + (t ^ (q >> 1)) * 4;
            uint4 aL[2], aH[2], bv[4];
#pragma unroll
            for (int i = 0; i < 2; i++) {
                aL[i] = *(const uint4*)(a_base + (16 * i) * FSTR + sw);
                aH[i] = *(const uint4*)(a_base + (16 * i + 8) * FSTR + sw);
            }
#pragma unroll
            for (int j = 0; j < 4; j++)
                bv[j] = *(const uint4*)(b_base0 + (8 * j) * FSTR + sw);
#pragma unroll
            for (int i = 0; i < 2; i++)
#pragma unroll
                for (int j = 0; j < 4; j++) {
                    mma_tf32(acc[i][j], aL[i].x, aH[i].x, aL[i].y, aH[i].y,
                             bv[j].x, bv[j].y);
                    mma_tf32(acc[i][j], aL[i].z, aH[i].z, aL[i].w, aH[i].w,
                             bv[j].z, bv[j].w);
                }
        }
        __syncthreads();

        // ---------- Phase 1 fill: edge features ----------
        {
            const float4* p = (const float4*)(ef + (size_t)eg * 128 + qh * 32);
            float x[32];
#pragma unroll
            for (int i = 0; i < 8; i++) {
                float4 v = p[i];
                x[4 * i] = v.x; x[4 * i + 1] = v.y; x[4 * i + 2] = v.z; x[4 * i + 3] = v.w;
            }
#pragma unroll
            for (int qp = 0; qp < 2; qp++) {
                const int q = 2 * qh + qp;
#pragma unroll
                for (int tt = 0; tt < 4; tt++) {
                    uint4 u = tf32q(x[16 * qp + tt], x[16 * qp + tt + 4],
                                    x[16 * qp + tt + 8], x[16 * qp + tt + 12]);
                    *(uint4*)(arow + q * 16 + (tt ^ qh) * 4) = u;
                }
            }
        }
        __syncthreads();

        // ---------- MMA phase 1 ----------
#pragma unroll
        for (int q = 0; q < 8; q++) {
            const int sw = q * 16 + (t ^ (q >> 1)) * 4;
            uint4 aL[2], aH[2], bv[4];
#pragma unroll
            for (int i = 0; i < 2; i++) {
                aL[i] = *(const uint4*)(a_base + (16 * i) * FSTR + sw);
                aH[i] = *(const uint4*)(a_base + (16 * i + 8) * FSTR + sw);
            }
#pragma unroll
            for (int j = 0; j < 4; j++)
                bv[j] = *(const uint4*)(b_base1 + (8 * j) * FSTR + sw);
#pragma unroll
            for (int i = 0; i < 2; i++)
#pragma unroll
                for (int j = 0; j < 4; j++) {
                    mma_tf32(acc[i][j], aL[i].x, aH[i].x, aL[i].y, aH[i].y,
                             bv[j].x, bv[j].y);
                    mma_tf32(acc[i][j], aL[i].z, aH[i].z, aL[i].w, aH[i].w,
                             bv[j].z, bv[j].w);
                }
        }

        // ---------- Epilogue: bias + relu + store ----------
#pragma unroll
        for (int j = 0; j < 4; j++) {
            const int col = nw + 8 * j + 2 * t;
            const float b0 = bsm[col], b1 = bsm[col + 1];
#pragma unroll
            for (int i = 0; i < 2; i++) {
                const int r0 = e0 + mw + 16 * i + g;
                if (r0 < E) {
                    float2 o;
                    o.x = fmaxf(acc[i][j][0] + b0, 0.f);
                    o.y = fmaxf(acc[i][j][1] + b1, 0.f);
                    *(float2*)(out + (size_t)r0 * 128 + col) = o;
                }
                if (r0 + 8 < E) {
                    float2 o;
                    o.x = fmaxf(acc[i][j][2] + b0, 0.f);
                    o.y = fmaxf(acc[i][j][3] + b1, 0.f);
                    *(float2*)(out + (size_t)(r0 + 8) * 128 + col) = o;
                }
            }
        }
        __syncthreads();   // As must be fully consumed before next tile's fill
    }
}

extern "C" void kernel_launch(void* const* d_in, const int* in_sizes, int n_in,
                              void* d_out, int out_size) {
    const float* nf = (const float*)d_in[0];
    const int*   ei = (const int*)d_in[1];
    const float* ef = (const float*)d_in[2];
    const float* W  = (const float*)d_in[3];
    const float* b  = (const float*)d_in[4];
    float* out = (float*)d_out;

    const int E = in_sizes[2] / 128;

    cudaFuncSetAttribute(edge_update_kernel,
                         cudaFuncAttributeMaxDynamicSharedMemorySize, SM_BYTES);

    int dev = 0, sms = 148;
    cudaGetDevice(&dev);
    cudaDeviceGetAttribute(&sms, cudaDevAttrMultiProcessorCount, dev);

    const int ntiles = (E + 127) / 128;
    const int grid = (sms < ntiles) ? sms : ntiles;

    edge_update_kernel<<<grid, 512, SM_BYTES>>>(nf, ei, ef, W, b, out, E);
}

// round 5
// speedup vs baseline: 1.2134x; 1.1012x over previous
#include <cuda_runtime.h>
#include <cstdint>

// ============================================================================
// EdgeUpdate: out[e] = relu( concat(nf[src[e]]+nf[dst[e]], ef[e]) @ W^T + b )
// GEMM: M=E (640000), N=128, K=256. tf32 mma.m16n8k8, fp32 accumulate.
//
// R5: 384 threads = 3 independent groups x 4 warps. Each group processes its
// own 64-edge sub-tile (2 serial K-phases) with group-scoped named barriers,
// so the 3 groups naturally pipeline fill (LDG/STS) against MMA (LDS/HMMA).
// Warp tile 64x32 (1M x 4N per group): B fragments read once per group,
// A x4 -> 25% less LDS traffic than 32x32 tiles.
//
// smem layout (FSTR=128 words/row + XOR swizzle, conflict-free for frag
// LDS.128 and fill STS.128):
//   word(row,q,t) = row*128 + ((q ^ (row&7))<<4) + ((t ^ (((q>>1)+(row>>1))&3))<<2)
//   entry(q,t) packs k = {16q+t, +4, +8, +12}
// ============================================================================

static constexpr int SMB_BIAS = 0;          // 128 floats
static constexpr int SMB_W    = 512;        // 2 phases x 128 rows x 512B = 131072
static constexpr int SMB_A    = 512 + 131072;   // 3 groups x 64 rows x 512B = 98304
static constexpr int SM_BYTES = SMB_A + 98304;  // 229888

#define CVT_TF32(u, f) asm("cvt.rna.tf32.f32 %0, %1;" : "=r"(u) : "f"(f))

__device__ __forceinline__ void mma_tf32(float* d, uint32_t a0, uint32_t a1,
                                         uint32_t a2, uint32_t a3,
                                         uint32_t b0, uint32_t b1) {
    asm volatile(
        "mma.sync.aligned.m16n8k8.row.col.f32.tf32.tf32.f32 "
        "{%0,%1,%2,%3}, {%4,%5,%6,%7}, {%8,%9}, {%0,%1,%2,%3};"
        : "+f"(d[0]), "+f"(d[1]), "+f"(d[2]), "+f"(d[3])
        : "r"(a0), "r"(a1), "r"(a2), "r"(a3), "r"(b0), "r"(b1));
}

// Store one 32-k chunk (x[0..31] fp32) of row `row` as packed tf32 entries.
// kbase32 = which 32-k chunk within the 128-k phase (0..3).
__device__ __forceinline__ void store_chunk(char* arow, int row, int kbase32,
                                            const float* x) {
    const int r7  = row & 7;
    const int rh2 = (row >> 1) & 3;
#pragma unroll
    for (int qp = 0; qp < 2; qp++) {
        const int q = kbase32 * 2 + qp;
        const uint32_t chunk = (uint32_t)((q ^ r7) << 6);
        char* cp = arow + chunk;
#pragma unroll
        for (int tt = 0; tt < 4; tt++) {
            const int slot = (tt ^ (((q >> 1) + rh2) & 3));
            uint32_t u0, u1, u2, u3;
            CVT_TF32(u0, x[16 * qp + tt]);
            CVT_TF32(u1, x[16 * qp + tt + 4]);
            CVT_TF32(u2, x[16 * qp + tt + 8]);
            CVT_TF32(u3, x[16 * qp + tt + 12]);
            *(uint4*)(cp + slot * 16) = make_uint4(u0, u1, u2, u3);
        }
    }
}

__global__ void __launch_bounds__(384, 1)
edge_update_kernel(const float* __restrict__ nf,
                   const int* __restrict__ ei,      // int32[2*E] (JAX x64 off)
                   const float* __restrict__ ef,
                   const float* __restrict__ W,
                   const float* __restrict__ bias,
                   float* __restrict__ out, int E) {
    extern __shared__ char smem[];
    float* bsm = (float*)(smem + SMB_BIAS);
    char*  Ws  = smem + SMB_W;
    char*  As  = smem + SMB_A;

    const int tid = threadIdx.x;
    const int wid = tid >> 5;
    const int lid = tid & 31;
    const int g   = lid >> 2;          // 0..7
    const int t   = lid & 3;           // 0..3
    const int gid = wid >> 2;          // group 0..2
    const int w   = wid & 3;           // warp in group
    const int nw  = w * 32;            // N strip
    const int tg  = tid & 127;         // thread in group

    if (tid < 128) bsm[tid] = bias[tid];

    // ---- One-time: W -> packed tf32 smem (2 phase arrays) ----
    for (int task = tid; task < 256; task += 384) {
        const int row = task & 127;        // W row (n)
        const int p   = task >> 7;         // phase (k half)
        char* wrow = Ws + p * 65536 + row * 512;
        const float* src = W + row * 256 + p * 128;
#pragma unroll 1
        for (int c = 0; c < 4; c++) {
            float x[32];
            const float4* sp = (const float4*)(src + c * 32);
#pragma unroll
            for (int i = 0; i < 8; i++) {
                float4 v = sp[i];
                x[4 * i] = v.x; x[4 * i + 1] = v.y;
                x[4 * i + 2] = v.z; x[4 * i + 3] = v.w;
            }
            store_chunk(wrow, row, c, x);
        }
    }
    __syncthreads();

    // ---- Precompute per-thread addresses ----
    char* Ag = As + gid * 32768;                   // group A array (64 rows)
    // fill role: row = tg>>1 (0..63), h = tg&1 (k half: 64 floats)
    const int frow = tg >> 1;
    const int fh   = tg & 1;
    char* arow = Ag + frow * 512;

    // fragment base pointers (rows fixed per lane forever)
    const char* paL[4]; const char* paH[4]; const char* pb[4];
#pragma unroll
    for (int i = 0; i < 4; i++) {
        paL[i] = Ag + (16 * i + g) * 512;
        paH[i] = Ag + (16 * i + 8 + g) * 512;
        pb[i]  = Ws + (nw + 8 * i + g) * 512;      // phase 0; +65536 for phase 1
    }
    const int gh = (g >> 1) & 3;   // (row>>1)&3 is identical for all frag rows

    const int barid = gid + 1;
    const int ntiles = (E + 191) / 192;

    for (int tile = blockIdx.x; tile < ntiles; tile += gridDim.x) {
        const int e0g = tile * 192 + gid * 64;     // group's first edge
        const int e   = e0g + frow;
        const int eg  = (e < E) ? e : (E - 1);

        float acc[4][4][4] = {};

        // ---------------- Phase 0 fill: nf[src] + nf[dst] ----------------
        {
            const int s  = ei[eg];
            const int dd = ei[(size_t)E + eg];
            const float* sp = nf + (size_t)s  * 128 + fh * 64;
            const float* dp = nf + (size_t)dd * 128 + fh * 64;
#pragma unroll
            for (int c = 0; c < 2; c++) {
                float x[32];
                const float4* s4 = (const float4*)(sp + c * 32);
                const float4* d4 = (const float4*)(dp + c * 32);
#pragma unroll
                for (int i = 0; i < 8; i++) {
                    float4 a = s4[i], b = d4[i];
                    x[4 * i]     = a.x + b.x; x[4 * i + 1] = a.y + b.y;
                    x[4 * i + 2] = a.z + b.z; x[4 * i + 3] = a.w + b.w;
                }
                store_chunk(arow, frow, fh * 2 + c, x);
            }
        }
        asm volatile("bar.sync %0, 128;" :: "r"(barid) : "memory");

        // ---------------- MMA phase 0 ----------------
#pragma unroll
        for (int q = 0; q < 8; q++) {
            const uint32_t off = (uint32_t)(((q ^ g) << 6) +
                                            ((t ^ (((q >> 1) + gh) & 3)) << 4));
            uint4 aL[4], aH[4], bv[4];
#pragma unroll
            for (int i = 0; i < 4; i++) {
                aL[i] = *(const uint4*)(paL[i] + off);
                aH[i] = *(const uint4*)(paH[i] + off);
                bv[i] = *(const uint4*)(pb[i] + off);
            }
#pragma unroll
            for (int i = 0; i < 4; i++)
#pragma unroll
                for (int j = 0; j < 4; j++) {
                    mma_tf32(acc[i][j], aL[i].x, aH[i].x, aL[i].y, aH[i].y,
                             bv[j].x, bv[j].y);
                    mma_tf32(acc[i][j], aL[i].z, aH[i].z, aL[i].w, aH[i].w,
                             bv[j].z, bv[j].w);
                }
        }
        asm volatile("bar.sync %0, 128;" :: "r"(barid) : "memory");

        // ---------------- Phase 1 fill: edge features ----------------
        {
            const float* p = ef + (size_t)eg * 128 + fh * 64;
#pragma unroll
            for (int c = 0; c < 2; c++) {
                float x[32];
                const float4* p4 = (const float4*)(p + c * 32);
#pragma unroll
                for (int i = 0; i < 8; i++) {
                    float4 v = p4[i];
                    x[4 * i] = v.x; x[4 * i + 1] = v.y;
                    x[4 * i + 2] = v.z; x[4 * i + 3] = v.w;
                }
                store_chunk(arow, frow, fh * 2 + c, x);
            }
        }
        asm volatile("bar.sync %0, 128;" :: "r"(barid) : "memory");

        // ---------------- MMA phase 1 ----------------
#pragma unroll
        for (int q = 0; q < 8; q++) {
            const uint32_t off = (uint32_t)(((q ^ g) << 6) +
                                            ((t ^ (((q >> 1) + gh) & 3)) << 4));
            uint4 aL[4], aH[4], bv[4];
#pragma unroll
            for (int i = 0; i < 4; i++) {
                aL[i] = *(const uint4*)(paL[i] + off);
                aH[i] = *(const uint4*)(paH[i] + off);
                bv[i] = *(const uint4*)(pb[i] + 65536 + off);
            }
#pragma unroll
            for (int i = 0; i < 4; i++)
#pragma unroll
                for (int j = 0; j < 4; j++) {
                    mma_tf32(acc[i][j], aL[i].x, aH[i].x, aL[i].y, aH[i].y,
                             bv[j].x, bv[j].y);
                    mma_tf32(acc[i][j], aL[i].z, aH[i].z, aL[i].w, aH[i].w,
                             bv[j].z, bv[j].w);
                }
        }
        asm volatile("bar.sync %0, 128;" :: "r"(barid) : "memory");
        // (A reads complete; epilogue below overlaps next tile's fill freely)

        // ---------------- Epilogue: bias + relu + store ----------------
#pragma unroll
        for (int j = 0; j < 4; j++) {
            const int col = nw + 8 * j + 2 * t;
            const float b0 = bsm[col], b1 = bsm[col + 1];
#pragma unroll
            for (int i = 0; i < 4; i++) {
                const int r0 = e0g + 16 * i + g;
                if (r0 < E) {
                    float2 o;
                    o.x = fmaxf(acc[i][j][0] + b0, 0.f);
                    o.y = fmaxf(acc[i][j][1] + b1, 0.f);
                    *(float2*)(out + (size_t)r0 * 128 + col) = o;
                }
                if (r0 + 8 < E) {
                    float2 o;
                    o.x = fmaxf(acc[i][j][2] + b0, 0.f);
                    o.y = fmaxf(acc[i][j][3] + b1, 0.f);
                    *(float2*)(out + (size_t)(r0 + 8) * 128 + col) = o;
                }
            }
        }
    }
}

extern "C" void kernel_launch(void* const* d_in, const int* in_sizes, int n_in,
                              void* d_out, int out_size) {
    const float* nf = (const float*)d_in[0];
    const int*   ei = (const int*)d_in[1];
    const float* ef = (const float*)d_in[2];
    const float* W  = (const float*)d_in[3];
    const float* b  = (const float*)d_in[4];
    float* out = (float*)d_out;

    const int E = in_sizes[2] / 128;

    cudaFuncSetAttribute(edge_update_kernel,
                         cudaFuncAttributeMaxDynamicSharedMemorySize, SM_BYTES);

    int dev = 0, sms = 148;
    cudaGetDevice(&dev);
    cudaDeviceGetAttribute(&sms, cudaDevAttrMultiProcessorCount, dev);

    const int ntiles = (E + 191) / 192;
    const int grid = (sms < ntiles) ? sms : ntiles;

    edge_update_kernel<<<grid, 384, SM_BYTES>>>(nf, ei, ef, W, b, out, E);
}

// round 6
// speedup vs baseline: 1.2233x; 1.0082x over previous
#include <cuda_runtime.h>
#include <cstdint>

// ============================================================================
// EdgeUpdate: out[e] = relu( concat(nf[src[e]]+nf[dst[e]], ef[e]) @ W^T + b )
// GEMM: M=E (640000), N=128, K=256. tf32 mma.m16n8k8, fp32 accumulate.
//
// R6: 3 groups x 4 warps, 64-edge tiles, 64x32 warp tiles (B read once).
// K split into 4 sub-phases of 64 with DOUBLE-BUFFERED A per group (2x16KB):
// each step issues next sub-phase LDGs, runs MMA on current buffer, then
// cvt+STS into the other buffer -> fills hidden under MMA, incl. across tiles
// (next tile's indices/gather prefetched during p2/p3).
//
// A swizzle (64-k rows, 256B): addr(r,q,t) = r*256 + ((q^(r&3))<<6)
//   + ((t ^ (q>>1) ^ (((r>>1)&1)<<1))<<4); entry packs k={16q+t,+4,+8,+12}.
// W swizzle (128-k rows, 512B) unchanged from R5 (verified).
// ============================================================================

static constexpr int SMB_BIAS = 0;
static constexpr int SMB_W    = 512;              // 2 x 65536
static constexpr int SMB_A    = 512 + 131072;     // 3 groups x 2 bufs x 16384
static constexpr int SM_BYTES = SMB_A + 3 * 32768;   // 229888

#define CVT_TF32(u, f) asm("cvt.rna.tf32.f32 %0, %1;" : "=r"(u) : "f"(f))

__device__ __forceinline__ void mma_tf32(float* d, uint32_t a0, uint32_t a1,
                                         uint32_t a2, uint32_t a3,
                                         uint32_t b0, uint32_t b1) {
    asm volatile(
        "mma.sync.aligned.m16n8k8.row.col.f32.tf32.tf32.f32 "
        "{%0,%1,%2,%3}, {%4,%5,%6,%7}, {%8,%9}, {%0,%1,%2,%3};"
        : "+f"(d[0]), "+f"(d[1]), "+f"(d[2]), "+f"(d[3])
        : "r"(a0), "r"(a1), "r"(a2), "r"(a3), "r"(b0), "r"(b1));
}

// W store: 128-k rows (8 chunks of 64B), swizzle chunk=q^(row&7),
// slot=t^(((q>>1)+(row>>1))&3)   [R5-verified]
__device__ __forceinline__ void store_w_chunk(char* wrow, int row, int kbase32,
                                              const float* x) {
    const int r7  = row & 7;
    const int rh2 = (row >> 1) & 3;
#pragma unroll
    for (int qp = 0; qp < 2; qp++) {
        const int q = kbase32 * 2 + qp;
        char* cp = wrow + ((q ^ r7) << 6);
#pragma unroll
        for (int tt = 0; tt < 4; tt++) {
            const int slot = (tt ^ (((q >> 1) + rh2) & 3));
            uint32_t u0, u1, u2, u3;
            CVT_TF32(u0, x[16 * qp + tt]);
            CVT_TF32(u1, x[16 * qp + tt + 4]);
            CVT_TF32(u2, x[16 * qp + tt + 8]);
            CVT_TF32(u3, x[16 * qp + tt + 12]);
            *(uint4*)(cp + slot * 16) = make_uint4(u0, u1, u2, u3);
        }
    }
}

__global__ void __launch_bounds__(384, 1)
edge_update_kernel(const float* __restrict__ nf,
                   const int* __restrict__ ei,      // int32[2*E] (JAX x64 off)
                   const float* __restrict__ ef,
                   const float* __restrict__ W,
                   const float* __restrict__ bias,
                   float* __restrict__ out, int E) {
    extern __shared__ char smem[];
    float* bsm = (float*)(smem + SMB_BIAS);
    char*  Ws  = smem + SMB_W;
    char*  As  = smem + SMB_A;

    const int tid = threadIdx.x;
    const int wid = tid >> 5;
    const int lid = tid & 31;
    const int g   = lid >> 2;
    const int t   = lid & 3;
    const int gid = wid >> 2;          // group 0..2
    const int nw  = (wid & 3) * 32;    // N strip
    const int tg  = tid & 127;

    if (tid < 128) bsm[tid] = bias[tid];

    // ---- One-time: W -> packed tf32 smem (2 k-phase arrays) ----
    for (int task = tid; task < 256; task += 384) {
        const int row = task & 127;
        const int p   = task >> 7;
        char* wrow = Ws + p * 65536 + row * 512;
        const float* src = W + row * 256 + p * 128;
#pragma unroll 1
        for (int c = 0; c < 4; c++) {
            float x[32];
            const float4* sp = (const float4*)(src + c * 32);
#pragma unroll
            for (int i = 0; i < 8; i++) {
                float4 v = sp[i];
                x[4 * i] = v.x; x[4 * i + 1] = v.y;
                x[4 * i + 2] = v.z; x[4 * i + 3] = v.w;
            }
            store_w_chunk(wrow, row, c, x);
        }
    }
    __syncthreads();

    // ---- Per-thread constants ----
    char* Ag = As + gid * 32768;               // 2 buffers of 16384
    const int frow = tg >> 1;                  // fill row 0..63
    const int fh   = tg & 1;                   // fill k-half (32 of 64)
    const int rb2  = ((frow >> 1) & 1) << 1;
    const int fr3  = frow & 3;
    char* arow = Ag + frow * 256;

    const char* paL[4]; const char* paH[4]; const char* pb[4];
#pragma unroll
    for (int i = 0; i < 4; i++) {
        paL[i] = Ag + (16 * i + g) * 256;
        paH[i] = Ag + (16 * i + 8 + g) * 256;
        pb[i]  = Ws + (nw + 8 * i + g) * 512;
    }
    const int gh  = (g >> 1) & 3;
    const int gb2 = ((g >> 1) & 1) << 1;
    const int ga3 = g & 3;
    const int barid = gid + 1;
    const int ntiles = (E + 191) / 192;

    // fill: gather nf[s]+nf[dd], sub-k-half sp (0/1) -> x[32]
    auto fill_nf = [&](int s, int dd, int sp, float* x) {
        const float4* s4 = (const float4*)(nf + (size_t)s  * 128 + sp * 64 + fh * 32);
        const float4* d4 = (const float4*)(nf + (size_t)dd * 128 + sp * 64 + fh * 32);
#pragma unroll
        for (int i = 0; i < 8; i++) {
            float4 a = s4[i], b = d4[i];
            x[4 * i]     = a.x + b.x; x[4 * i + 1] = a.y + b.y;
            x[4 * i + 2] = a.z + b.z; x[4 * i + 3] = a.w + b.w;
        }
    };
    auto fill_ef = [&](int eg, int sp, float* x) {
        const float4* p4 = (const float4*)(ef + (size_t)eg * 128 + sp * 64 + fh * 32);
#pragma unroll
        for (int i = 0; i < 8; i++) {
            float4 v = p4[i];
            x[4 * i] = v.x; x[4 * i + 1] = v.y;
            x[4 * i + 2] = v.z; x[4 * i + 3] = v.w;
        }
    };
    // cvt + STS x[32] into buffer bsel (this thread's 2 q-chunks)
    auto sts_x = [&](int bsel, const float* x) {
        char* base = arow + bsel * 16384;
#pragma unroll
        for (int qp = 0; qp < 2; qp++) {
            const int q = 2 * fh + qp;
            char* cp = base + ((q ^ fr3) << 6);
#pragma unroll
            for (int tt = 0; tt < 4; tt++) {
                const int slot = tt ^ (q >> 1) ^ rb2;
                uint32_t u0, u1, u2, u3;
                CVT_TF32(u0, x[16 * qp + tt]);
                CVT_TF32(u1, x[16 * qp + tt + 4]);
                CVT_TF32(u2, x[16 * qp + tt + 8]);
                CVT_TF32(u3, x[16 * qp + tt + 12]);
                *(uint4*)(cp + slot * 16) = make_uint4(u0, u1, u2, u3);
            }
        }
    };
    // MMA one sub-phase: A buffer bsel, W phase wph, W q-offset qg0
    auto mma_sub = [&](int bsel, int wph, int qg0, float (*acc)[4][4]) {
        const uint32_t bofs = (uint32_t)(bsel * 16384);
        const uint32_t wpho = (uint32_t)(wph * 65536);
#pragma unroll
        for (int q = 0; q < 4; q++) {
            const uint32_t aoff = bofs + (uint32_t)(((q ^ ga3) << 6) +
                                  ((t ^ (q >> 1) ^ gb2) << 4));
            const int qg = qg0 + q;
            const uint32_t woff = wpho + (uint32_t)(((qg ^ g) << 6) +
                                  ((t ^ (((qg >> 1) + gh) & 3)) << 4));
            uint4 aL[4], aH[4], bv[4];
#pragma unroll
            for (int i = 0; i < 4; i++) {
                aL[i] = *(const uint4*)(paL[i] + aoff);
                aH[i] = *(const uint4*)(paH[i] + aoff);
                bv[i] = *(const uint4*)(pb[i] + woff);
            }
#pragma unroll
            for (int i = 0; i < 4; i++)
#pragma unroll
                for (int j = 0; j < 4; j++) {
                    mma_tf32(acc[i][j], aL[i].x, aH[i].x, aL[i].y, aH[i].y,
                             bv[j].x, bv[j].y);
                    mma_tf32(acc[i][j], aL[i].z, aH[i].z, aL[i].w, aH[i].w,
                             bv[j].z, bv[j].w);
                }
        }
    };

    // ---- Prologue: fill buf0 with first tile's nf sub-phase 0 ----
    int tile = blockIdx.x;
    if (tile >= ntiles) return;
    int e0g = tile * 192 + gid * 64;
    int e   = e0g + frow;
    int eg  = (e < E) ? e : (E - 1);
    int s   = ei[eg];
    int dd  = ei[(size_t)E + eg];
    float xf[32];
    fill_nf(s, dd, 0, xf);
    sts_x(0, xf);
    asm volatile("bar.sync %0, 128;" :: "r"(barid) : "memory");

    while (true) {
        float acc[4][4][4] = {};

        // p0: MMA buf0 (K 0-63); prefetch nf K 64-127
        fill_nf(s, dd, 1, xf);
        mma_sub(0, 0, 0, acc);
        sts_x(1, xf);
        asm volatile("bar.sync %0, 128;" :: "r"(barid) : "memory");

        // p1: MMA buf1 (K 64-127); prefetch ef K 0-63
        fill_ef(eg, 0, xf);
        mma_sub(1, 0, 4, acc);
        sts_x(0, xf);
        asm volatile("bar.sync %0, 128;" :: "r"(barid) : "memory");

        // p2: MMA buf0 (K 128-191); prefetch ef K 64-127 + next indices
        fill_ef(eg, 1, xf);
        const int ntile = tile + gridDim.x;
        const int ne0g  = ntile * 192 + gid * 64;
        int neg = 0;
        if (ntile < ntiles) {
            const int ne = ne0g + frow;
            neg = (ne < E) ? ne : (E - 1);
        }
        const int ns  = ei[neg];
        const int ndd = ei[(size_t)E + neg];
        mma_sub(0, 1, 0, acc);
        sts_x(1, xf);
        asm volatile("bar.sync %0, 128;" :: "r"(barid) : "memory");

        // p3: MMA buf1 (K 192-255); prefetch NEXT tile's nf K 0-63 -> buf0
        fill_nf(ns, ndd, 0, xf);
        mma_sub(1, 1, 4, acc);
        sts_x(0, xf);
        asm volatile("bar.sync %0, 128;" :: "r"(barid) : "memory");

        // ---- Epilogue: bias + relu + store ----
#pragma unroll
        for (int j = 0; j < 4; j++) {
            const int col = nw + 8 * j + 2 * t;
            const float b0 = bsm[col], b1 = bsm[col + 1];
#pragma unroll
            for (int i = 0; i < 4; i++) {
                const int r0 = e0g + 16 * i + g;
                if (r0 < E) {
                    float2 o;
                    o.x = fmaxf(acc[i][j][0] + b0, 0.f);
                    o.y = fmaxf(acc[i][j][1] + b1, 0.f);
                    *(float2*)(out + (size_t)r0 * 128 + col) = o;
                }
                if (r0 + 8 < E) {
                    float2 o;
                    o.x = fmaxf(acc[i][j][2] + b0, 0.f);
                    o.y = fmaxf(acc[i][j][3] + b1, 0.f);
                    *(float2*)(out + (size_t)(r0 + 8) * 128 + col) = o;
                }
            }
        }

        if (ntile >= ntiles) break;
        tile = ntile; e0g = ne0g; eg = neg; s = ns; dd = ndd;
    }
}

extern "C" void kernel_launch(void* const* d_in, const int* in_sizes, int n_in,
                              void* d_out, int out_size) {
    const float* nf = (const float*)d_in[0];
    const int*   ei = (const int*)d_in[1];
    const float* ef = (const float*)d_in[2];
    const float* W  = (const float*)d_in[3];
    const float* b  = (const float*)d_in[4];
    float* out = (float*)d_out;

    const int E = in_sizes[2] / 128;

    cudaFuncSetAttribute(edge_update_kernel,
                         cudaFuncAttributeMaxDynamicSharedMemorySize, SM_BYTES);

    int dev = 0, sms = 148;
    cudaGetDevice(&dev);
    cudaDeviceGetAttribute(&sms, cudaDevAttrMultiProcessorCount, dev);

    const int ntiles = (E + 191) / 192;
    const int grid = (sms < ntiles) ? sms : ntiles;

    edge_update_kernel<<<grid, 384, SM_BYTES>>>(nf, ei, ef, W, b, out, E);
}

// round 7
// speedup vs baseline: 1.8658x; 1.5252x over previous
#include <cuda_runtime.h>
#include <cstdint>

// ============================================================================
// EdgeUpdate: out[e] = relu( concat(nf[src[e]]+nf[dst[e]], ef[e]) @ W^T + b )
// GEMM: M=E (640000), N=128, K=256. tf32 mma.m16n8k8, fp32 accumulate.
//
// R7: fix global-access coalescing. Fill instructions now cover 2 rows x 256B
// contiguous (lanes 0-15 row r, 16-31 row r+2) -> 4 lines per LDG.128 instead
// of ~32. Scatter into the packed A layout via STS.32 (32 distinct banks:
// rows r/r+2 differ in bit1 -> rb2 differs -> slot sets disjoint).
// A layout, W layout, MMA, epilogue identical to R6.
//
// A entry (q,t) @ row*256 + ((q^(row&3))<<6) + ((t^(q>>1)^(((row>>1)&1)<<1))<<4)
//   position p (4B) holds k = 16q + t + 4p.
// Thread (lane l) holds k = 16q+4*pos+j, q=(l&15)>>2, pos=l&3 -> t=j, p=pos.
// ============================================================================

static constexpr int SMB_BIAS = 0;
static constexpr int SMB_W    = 512;              // 2 x 65536
static constexpr int SMB_A    = 512 + 131072;     // 3 groups x 2 bufs x 16384
static constexpr int SM_BYTES = SMB_A + 3 * 32768;   // 229888

#define CVT_TF32(u, f) asm("cvt.rna.tf32.f32 %0, %1;" : "=r"(u) : "f"(f))

__device__ __forceinline__ void mma_tf32(float* d, uint32_t a0, uint32_t a1,
                                         uint32_t a2, uint32_t a3,
                                         uint32_t b0, uint32_t b1) {
    asm volatile(
        "mma.sync.aligned.m16n8k8.row.col.f32.tf32.tf32.f32 "
        "{%0,%1,%2,%3}, {%4,%5,%6,%7}, {%8,%9}, {%0,%1,%2,%3};"
        : "+f"(d[0]), "+f"(d[1]), "+f"(d[2]), "+f"(d[3])
        : "r"(a0), "r"(a1), "r"(a2), "r"(a3), "r"(b0), "r"(b1));
}

// W store: 128-k rows (8 chunks of 64B), chunk=q^(row&7), slot=t^(((q>>1)+(row>>1))&3)
__device__ __forceinline__ void store_w_chunk(char* wrow, int row, int kbase32,
                                              const float* x) {
    const int r7  = row & 7;
    const int rh2 = (row >> 1) & 3;
#pragma unroll
    for (int qp = 0; qp < 2; qp++) {
        const int q = kbase32 * 2 + qp;
        char* cp = wrow + ((q ^ r7) << 6);
#pragma unroll
        for (int tt = 0; tt < 4; tt++) {
            const int slot = (tt ^ (((q >> 1) + rh2) & 3));
            uint32_t u0, u1, u2, u3;
            CVT_TF32(u0, x[16 * qp + tt]);
            CVT_TF32(u1, x[16 * qp + tt + 4]);
            CVT_TF32(u2, x[16 * qp + tt + 8]);
            CVT_TF32(u3, x[16 * qp + tt + 12]);
            *(uint4*)(cp + slot * 16) = make_uint4(u0, u1, u2, u3);
        }
    }
}

// row sub-base within 16-row warp strip for iteration it: {0,1,4,5,8,9,12,13}
#define RBASE(it) ((((it) >> 1) << 2) | ((it) & 1))

__global__ void __launch_bounds__(384, 1)
edge_update_kernel(const float* __restrict__ nf,
                   const int* __restrict__ ei,      // int32[2*E] (JAX x64 off)
                   const float* __restrict__ ef,
                   const float* __restrict__ W,
                   const float* __restrict__ bias,
                   float* __restrict__ out, int E) {
    extern __shared__ char smem[];
    float* bsm = (float*)(smem + SMB_BIAS);
    char*  Ws  = smem + SMB_W;
    char*  As  = smem + SMB_A;

    const int tid = threadIdx.x;
    const int wid = tid >> 5;
    const int lid = tid & 31;
    const int g   = lid >> 2;
    const int t   = lid & 3;
    const int gid = wid >> 2;          // group 0..2
    const int w4  = wid & 3;           // warp in group = N strip
    const int nw  = w4 * 32;

    if (tid < 128) bsm[tid] = bias[tid];

    // ---- One-time: W -> packed tf32 smem (2 k-phase arrays) ----
    for (int task = tid; task < 256; task += 384) {
        const int row = task & 127;
        const int p   = task >> 7;
        char* wrow = Ws + p * 65536 + row * 512;
        const float* src = W + row * 256 + p * 128;
#pragma unroll 1
        for (int c = 0; c < 4; c++) {
            float x[32];
            const float4* sp = (const float4*)(src + c * 32);
#pragma unroll
            for (int i = 0; i < 8; i++) {
                float4 v = sp[i];
                x[4 * i] = v.x; x[4 * i + 1] = v.y;
                x[4 * i + 2] = v.z; x[4 * i + 3] = v.w;
            }
            store_w_chunk(wrow, row, c, x);
        }
    }
    __syncthreads();

    // ---- Per-thread constants ----
    char* Ag = As + gid * 32768;               // 2 buffers of 16384
    const int hl   = lid >> 4;                 // row-pair half
    const int c16  = lid & 15;                 // 16B column in 256B sub-row
    const int q    = c16 >> 2;                 // A q-chunk (const)
    const int pos4 = (lid & 3) << 2;           // entry byte position
    const int row0 = 16 * w4 + 2 * hl;         // base row for this lane

    const char* paL[4]; const char* paH[4]; const char* pb[4];
#pragma unroll
    for (int i = 0; i < 4; i++) {
        paL[i] = Ag + (16 * i + g) * 256;
        paH[i] = Ag + (16 * i + 8 + g) * 256;
        pb[i]  = Ws + (nw + 8 * i + g) * 512;
    }
    const int gh  = (g >> 1) & 3;
    const int gb2 = ((g >> 1) & 1) << 1;
    const int ga3 = g & 3;
    const int barid = gid + 1;
    const int ntiles = (E + 191) / 192;

    // preload this lane's 8 (src,dst) index pairs for a tile
    auto load_idx = [&](int base_e, int* sI, int* dI) {
#pragma unroll
        for (int it = 0; it < 8; it++) {
            int e = base_e + row0 + RBASE(it);
            int eg2 = (e < E) ? e : (E - 1);
            sI[it] = ei[eg2];
            dI[it] = ei[(size_t)E + eg2];
        }
    };
    auto fill_nf = [&](const int* sI, const int* dI, int sp, float* x) {
#pragma unroll
        for (int it = 0; it < 8; it++) {
            const float4 a = *(const float4*)(nf + (size_t)sI[it] * 128 + sp * 64 + c16 * 4);
            const float4 b = *(const float4*)(nf + (size_t)dI[it] * 128 + sp * 64 + c16 * 4);
            x[4 * it]     = a.x + b.x; x[4 * it + 1] = a.y + b.y;
            x[4 * it + 2] = a.z + b.z; x[4 * it + 3] = a.w + b.w;
        }
    };
    auto fill_ef = [&](int base_e, int sp, float* x) {
#pragma unroll
        for (int it = 0; it < 8; it++) {
            int e = base_e + row0 + RBASE(it);
            int eg2 = (e < E) ? e : (E - 1);
            const float4 v = *(const float4*)(ef + (size_t)eg2 * 128 + sp * 64 + c16 * 4);
            x[4 * it]     = v.x; x[4 * it + 1] = v.y;
            x[4 * it + 2] = v.z; x[4 * it + 3] = v.w;
        }
    };
    // scatter 32 floats (8 it x 4 consecutive k) into packed A buffer bsel
    auto sts_x = [&](int bsel, const float* x) {
        char* base = Ag + bsel * 16384;
#pragma unroll
        for (int it = 0; it < 8; it++) {
            const int row = row0 + RBASE(it);
            const int r3  = row & 3;
            const int rb2 = ((row >> 1) & 1) << 1;
            const int s0  = (q >> 1) ^ rb2;                  // disjoint bits
            char* p0 = base + row * 256 + (((q ^ r3) & 3) << 6) + (s0 << 4) + pos4;
#pragma unroll
            for (int j = 0; j < 4; j++) {
                uint32_t u; CVT_TF32(u, x[4 * it + j]);
                *(uint32_t*)((uintptr_t)p0 ^ (unsigned)(j << 4)) = u;
            }
        }
    };
    // MMA one sub-phase: A buffer bsel, W phase wph, W q-offset qg0
    auto mma_sub = [&](int bsel, int wph, int qg0, float (*acc)[4][4]) {
        const uint32_t bofs = (uint32_t)(bsel * 16384);
        const uint32_t wpho = (uint32_t)(wph * 65536);
#pragma unroll
        for (int qq = 0; qq < 4; qq++) {
            const uint32_t aoff = bofs + (uint32_t)(((qq ^ ga3) << 6) +
                                  ((t ^ (qq >> 1) ^ gb2) << 4));
            const int qg = qg0 + qq;
            const uint32_t woff = wpho + (uint32_t)(((qg ^ g) << 6) +
                                  ((t ^ (((qg >> 1) + gh) & 3)) << 4));
            uint4 aL[4], aH[4], bv[4];
#pragma unroll
            for (int i = 0; i < 4; i++) {
                aL[i] = *(const uint4*)(paL[i] + aoff);
                aH[i] = *(const uint4*)(paH[i] + aoff);
                bv[i] = *(const uint4*)(pb[i] + woff);
            }
#pragma unroll
            for (int i = 0; i < 4; i++)
#pragma unroll
                for (int j = 0; j < 4; j++) {
                    mma_tf32(acc[i][j], aL[i].x, aH[i].x, aL[i].y, aH[i].y,
                             bv[j].x, bv[j].y);
                    mma_tf32(acc[i][j], aL[i].z, aH[i].z, aL[i].w, aH[i].w,
                             bv[j].z, bv[j].w);
                }
        }
    };

    // ---- Prologue ----
    int tile = blockIdx.x;
    if (tile >= ntiles) return;
    int e0g = tile * 192 + gid * 64;
    int sI[8], dI[8];
    load_idx(e0g, sI, dI);
    float xf[32];
    fill_nf(sI, dI, 0, xf);
    sts_x(0, xf);
    asm volatile("bar.sync %0, 128;" :: "r"(barid) : "memory");

    while (true) {
        float acc[4][4][4] = {};

        // p0: MMA buf0 (K 0-63); prefetch nf K 64-127 (last use of sI/dI)
        fill_nf(sI, dI, 1, xf);
        mma_sub(0, 0, 0, acc);
        sts_x(1, xf);
        asm volatile("bar.sync %0, 128;" :: "r"(barid) : "memory");

        // p1: MMA buf1 (K 64-127); prefetch ef K 0-63 + NEXT tile's indices
        const int ntile = tile + gridDim.x;
        const int ne0g  = ntile * 192 + gid * 64;
        fill_ef(e0g, 0, xf);
        load_idx(ne0g, sI, dI);          // clamped; harmless past end
        mma_sub(1, 0, 4, acc);
        sts_x(0, xf);
        asm volatile("bar.sync %0, 128;" :: "r"(barid) : "memory");

        // p2: MMA buf0 (K 128-191); prefetch ef K 64-127
        fill_ef(e0g, 1, xf);
        mma_sub(0, 1, 0, acc);
        sts_x(1, xf);
        asm volatile("bar.sync %0, 128;" :: "r"(barid) : "memory");

        // p3: MMA buf1 (K 192-255); prefetch NEXT tile's nf K 0-63 -> buf0
        fill_nf(sI, dI, 0, xf);
        mma_sub(1, 1, 4, acc);
        sts_x(0, xf);
        asm volatile("bar.sync %0, 128;" :: "r"(barid) : "memory");

        // ---- Epilogue: bias + relu + store ----
#pragma unroll
        for (int j = 0; j < 4; j++) {
            const int col = nw + 8 * j + 2 * t;
            const float b0 = bsm[col], b1 = bsm[col + 1];
#pragma unroll
            for (int i = 0; i < 4; i++) {
                const int r0 = e0g + 16 * i + g;
                if (r0 < E) {
                    float2 o;
                    o.x = fmaxf(acc[i][j][0] + b0, 0.f);
                    o.y = fmaxf(acc[i][j][1] + b1, 0.f);
                    *(float2*)(out + (size_t)r0 * 128 + col) = o;
                }
                if (r0 + 8 < E) {
                    float2 o;
                    o.x = fmaxf(acc[i][j][2] + b0, 0.f);
                    o.y = fmaxf(acc[i][j][3] + b1, 0.f);
                    *(float2*)(out + (size_t)(r0 + 8) * 128 + col) = o;
                }
            }
        }

        if (ntile >= ntiles) break;
        tile = ntile; e0g = ne0g;
    }
}

extern "C" void kernel_launch(void* const* d_in, const int* in_sizes, int n_in,
                              void* d_out, int out_size) {
    const float* nf = (const float*)d_in[0];
    const int*   ei = (const int*)d_in[1];
    const float* ef = (const float*)d_in[2];
    const float* W  = (const float*)d_in[3];
    const float* b  = (const float*)d_in[4];
    float* out = (float*)d_out;

    const int E = in_sizes[2] / 128;

    cudaFuncSetAttribute(edge_update_kernel,
                         cudaFuncAttributeMaxDynamicSharedMemorySize, SM_BYTES);

    int dev = 0, sms = 148;
    cudaGetDevice(&dev);
    cudaDeviceGetAttribute(&sms, cudaDevAttrMultiProcessorCount, dev);

    const int ntiles = (E + 191) / 192;
    const int grid = (sms < ntiles) ? sms : ntiles;

    edge_update_kernel<<<grid, 384, SM_BYTES>>>(nf, ei, ef, W, b, out, E);
}